// round 12
// baseline (speedup 1.0000x reference)
#include <cuda_runtime.h>
#include <cuda_fp16.h>

// ---------------- geometry (fixed) -------------------------------------------
#define NCHANS   2560
#define T        256
#define CT       (NCHANS * T)        // 655360
#define NCELLS   40000
#define NCONTRIB (2 * NCELLS * 3)    // 240000
#define NSUB     8                   // sub-buckets per channel
#define NBUCKETS (NCHANS * NSUB)     // 20480

// ---------------- gather tiling ----------------------------------------------
#define TW       32                  // ticks per tile (16 half2 pairs)
#define NTILES   (T / TW)            // 8
#define GCH      64                  // channels per gather block
#define NCGRP    (NCHANS / GCH)      // 40
#define SXP      17                  // smem pair-stride (half2 units, ODD)
#define SX_BYTES (NCHANS * SXP * 4)  // 174080

typedef unsigned long long ull;

// ---------------- device scratch (static; no allocations) --------------------
__device__ int      g_scount[NBUCKETS];
__device__ int      g_scursor[NBUCKETS];
__device__ int      g_offsets[NBUCKETS + 1];
__device__ int2     g_meta[NCONTRIB];     // packed (ch0|ch1<<16, ch2) per contribution
__device__ unsigned g_xp[CT / 2];         // relu(x) fp16, pair-major: [t/2][ch]
__device__ float    g_M[6];               // collapsed W1@W2, M[p*2+o]
__device__ float    g_c[2];               // collapsed b1@W2 + b2

// ---------------- packed f32x2 helpers ---------------------------------------
__device__ __forceinline__ ull pack2(float lo, float hi) {
    ull r; asm("mov.b64 %0, {%1,%2};" : "=l"(r) : "f"(lo), "f"(hi)); return r;
}
__device__ __forceinline__ ull ffma2(ull a, ull b, ull c) {
    ull d; asm("fma.rn.f32x2 %0, %1, %2, %3;" : "=l"(d) : "l"(a), "l"(b), "l"(c));
    return d;
}
__device__ __forceinline__ void unpack2(ull v, float& lo, float& hi) {
    asm("mov.b64 {%0,%1}, %2;" : "=f"(lo), "=f"(hi) : "l"(v));
}

// ---------------- kernel A: prep — relu + fp16 pair-transpose + weights + zero
__global__ void prep_kernel(const float* __restrict__ x, float* __restrict__ out,
                            const float* __restrict__ W1, const float* __restrict__ b1,
                            const float* __restrict__ W2, const float* __restrict__ b2) {
    int b = blockIdx.x;
    if (b < 640) {
        __shared__ float tile[32][33];                   // tile[ch_local][t_local]
        int cht = b % 80, tt = b / 80;
        int ch0 = cht * 32, t0 = tt * 32;
        int tx = threadIdx.x & 31, ty = threadIdx.x >> 5;   // 32 x 8
        #pragma unroll
        for (int r = 0; r < 4; r++) {
            int ch = ch0 + ty + 8 * r;
            float v = fmaxf(x[ch * T + t0 + tx], 0.f);
            out[ch * T + t0 + tx] = v;                       // feature 0 exact fp32
            tile[ty + 8 * r][tx] = v;
        }
        __syncthreads();
        #pragma unroll
        for (int rr = 0; rr < 2; rr++) {
            int tp = ty + 8 * rr;                            // tick-pair 0..15 in tile
            __half2 h = __floats2half2_rn(tile[tx][2 * tp], tile[tx][2 * tp + 1]);
            g_xp[(t0 / 2 + tp) * NCHANS + ch0 + tx] = *(unsigned*)&h;
        }
    } else if (b == 640) {
        if (threadIdx.x < 6) {
            int p = threadIdx.x >> 1, o = threadIdx.x & 1;
            float s = 0.f;
            #pragma unroll
            for (int h = 0; h < 8; h++) s = fmaf(W1[p * 8 + h], W2[h * 2 + o], s);
            g_M[threadIdx.x] = s;
        } else if (threadIdx.x < 8) {
            int o = threadIdx.x - 6;
            float s = b2[o];
            #pragma unroll
            for (int h = 0; h < 8; h++) s = fmaf(b1[h], W2[h * 2 + o], s);
            g_c[o] = s;
        }
    } else {
        int idx = (b - 641) * 256 + threadIdx.x;
        if (idx < NBUCKETS) g_scount[idx] = 0;
    }
}

// ---------------- kernel B: count (1 thread per CONTRIBUTION) ----------------
__global__ void count_kernel(const int* __restrict__ gi0, const int* __restrict__ gi1,
                             const int* __restrict__ wc00, const int* __restrict__ wc01,
                             const int* __restrict__ wc02, const int* __restrict__ wc10,
                             const int* __restrict__ wc11, const int* __restrict__ wc12) {
    int e = blockIdx.x * blockDim.x + threadIdx.x;
    if (e >= NCONTRIB) return;
    int f = e / (NCELLS * 3);
    int r = e - f * (NCELLS * 3);         // cell*3 + p
    int p = r % 3;
    const int* gi = f ? gi1 : gi0;
    int w = __ldg(&gi[r]);
    const int* wc;
    if (f == 0) wc = (p == 0) ? wc00 : (p == 1) ? wc01 : wc02;
    else        wc = (p == 0) ? wc10 : (p == 1) ? wc11 : wc12;
    int ch = __ldg(&wc[2 * w + 1]);
    atomicAdd(&g_scount[ch * NSUB + (e & 7)], 1);
}

// ---------------- kernel C: exclusive scan over 20480 buckets + zero cursors -
__global__ void __launch_bounds__(1024) scan_kernel() {
    __shared__ int wsum[32];
    int th = threadIdx.x, lane = th & 31, w = th >> 5;   // 32 warps exactly
    int base = th * 20;
    int loc[20], tsum = 0;
    #pragma unroll
    for (int i = 0; i < 20; i++) { loc[i] = tsum; tsum += g_scount[base + i]; }
    int s = tsum;
    #pragma unroll
    for (int off = 1; off < 32; off <<= 1) {
        int n = __shfl_up_sync(0xFFFFFFFFu, s, off);
        if (lane >= off) s += n;
    }
    if (lane == 31) wsum[w] = s;
    __syncthreads();
    if (w == 0) {
        int v = wsum[lane];
        #pragma unroll
        for (int off = 1; off < 32; off <<= 1) {
            int n = __shfl_up_sync(0xFFFFFFFFu, v, off);
            if (lane >= off) v += n;
        }
        wsum[lane] = v;
    }
    __syncthreads();
    int warpbase = (w > 0) ? wsum[w - 1] : 0;
    int excl = warpbase + s - tsum;
    #pragma unroll
    for (int i = 0; i < 20; i++) {
        g_offsets[base + i] = excl + loc[i];
        g_scursor[base + i] = 0;
    }
    if (th == 1023) g_offsets[NBUCKETS] = wsum[31];
}

// ---------------- kernel D: CSR fill (1 thread per CONTRIBUTION) -------------
__global__ void fill_kernel(const int* __restrict__ gi0, const int* __restrict__ gi1,
                            const int* __restrict__ wc00, const int* __restrict__ wc01,
                            const int* __restrict__ wc02, const int* __restrict__ wc10,
                            const int* __restrict__ wc11, const int* __restrict__ wc12) {
    int e = blockIdx.x * blockDim.x + threadIdx.x;
    if (e >= NCONTRIB) return;
    int f = e / (NCELLS * 3);
    int r = e - f * (NCELLS * 3);
    int p = r % 3;
    int r0 = r - p;                        // cell base
    const int* gi = f ? gi1 : gi0;
    int w0 = __ldg(&gi[r0 + 0]);
    int w1 = __ldg(&gi[r0 + 1]);
    int w2 = __ldg(&gi[r0 + 2]);
    const int* wcU = f ? wc10 : wc00;
    const int* wcV = f ? wc11 : wc01;
    const int* wcW = f ? wc12 : wc02;
    int c0 = __ldg(&wcU[2 * w0 + 1]);
    int c1 = __ldg(&wcV[2 * w1 + 1]);
    int c2 = __ldg(&wcW[2 * w2 + 1]);
    int cp = (p == 0) ? c0 : (p == 1) ? c1 : c2;   // own channel
    int bkt = cp * NSUB + (e & 7);
    int pos = atomicAdd(&g_scursor[bkt], 1);
    g_meta[g_offsets[bkt] + pos] = make_int2(c0 | (c1 << 16), c2);
}

// ---------------- kernel E: fp16-slice gather + max --------------------------
// grid = NCGRP*NTILES = 320, 1024 threads. Block stages all 2560 channels x 16
// half2 tick-pairs (174080 B, pair-stride 17). Thread = one channel x one
// tick-pair; a warp spans only 2 channels (16 tick-lanes each) -> low loop
// divergence + 2-arc smem access pattern.
extern __shared__ unsigned sx2[];
__global__ void __launch_bounds__(1024) gather_kernel(float* __restrict__ out) {
    const int cgrp = blockIdx.x % NCGRP;
    const int tile = blockIdx.x / NCGRP;
    const int t0 = tile * TW;

    // stage slice: g_xp[(t0/2 + pr)*2560 + ch] -> sx2[ch*17 + pr]
    {
        const unsigned* __restrict__ src = g_xp + (t0 / 2) * NCHANS;
        int j = threadIdx.x, ch = threadIdx.x, pr = 0;
        #pragma unroll
        for (int k = 0; k < (NCHANS * (TW / 2)) / 1024; k++) {   // 40 iters
            sx2[ch * SXP + pr] = __ldg(src + j);
            j += 1024; ch += 1024;
            if (ch >= NCHANS) { ch -= NCHANS; ++pr; }
        }
    }
    __syncthreads();

    const int tl = threadIdx.x & 15;         // tick-pair 0..15 -> ticks t0+2tl,+1
    const int cl = threadIdx.x >> 4;         // channel lane 0..63
    const int c  = cgrp * GCH + cl;

    const ull M00 = pack2(g_M[0], g_M[0]), M01 = pack2(g_M[1], g_M[1]);
    const ull M10 = pack2(g_M[2], g_M[2]), M11 = pack2(g_M[3], g_M[3]);
    const ull M20 = pack2(g_M[4], g_M[4]), M21 = pack2(g_M[5], g_M[5]);
    const ull K0  = pack2(g_c[0], g_c[0]),  K1  = pack2(g_c[1], g_c[1]);

    const int beg = g_offsets[c * NSUB], end = g_offsets[c * NSUB + NSUB];
    float mA0 = 0.f, mA1 = 0.f, mB0 = 0.f, mB1 = 0.f;

    const __half2* __restrict__ sxh = (const __half2*)sx2;

    #pragma unroll 2
    for (int i = beg; i < end; i++) {
        int2 mv = __ldg(&g_meta[i]);
        unsigned lo = (unsigned)mv.x;
        __half2 h0 = sxh[(lo & 0xFFFFu) * SXP + tl];
        __half2 h1 = sxh[(lo >> 16)     * SXP + tl];
        __half2 h2 = sxh[(unsigned)mv.y * SXP + tl];
        float2 f0 = __half22float2(h0);
        float2 f1 = __half22float2(h1);
        float2 f2 = __half22float2(h2);
        ull a0 = pack2(f0.x, f0.y);
        ull a1 = pack2(f1.x, f1.y);
        ull a2 = pack2(f2.x, f2.y);
        ull y0 = ffma2(a0, M00, ffma2(a1, M10, ffma2(a2, M20, K0)));
        ull y1 = ffma2(a0, M01, ffma2(a1, M11, ffma2(a2, M21, K1)));
        float y0a, y0b, y1a, y1b;
        unpack2(y0, y0a, y0b);
        unpack2(y1, y1a, y1b);
        mA0 = fmaxf(mA0, y0a); mB0 = fmaxf(mB0, y0b);
        mA1 = fmaxf(mA1, y1a); mB1 = fmaxf(mB1, y1b);
    }

    const int tA = t0 + 2 * tl;
    *(float2*)(out + CT + c * T + tA)     = make_float2(mA0, mB0);
    *(float2*)(out + 2 * CT + c * T + tA) = make_float2(mA1, mB1);
}

// ---------------- launch ------------------------------------------------------
extern "C" void kernel_launch(void* const* d_in, const int* in_sizes, int n_in,
                              void* d_out, int out_size) {
    const float* x   = (const float*)d_in[0];
    const float* W1  = (const float*)d_in[1];
    const float* b1  = (const float*)d_in[2];
    const float* W2  = (const float*)d_in[3];
    const float* b2  = (const float*)d_in[4];
    const int* gi0   = (const int*)d_in[5];
    const int* gi1   = (const int*)d_in[6];
    const int* wc00  = (const int*)d_in[7];
    const int* wc01  = (const int*)d_in[8];
    const int* wc02  = (const int*)d_in[9];
    const int* wc10  = (const int*)d_in[10];
    const int* wc11  = (const int*)d_in[11];
    const int* wc12  = (const int*)d_in[12];
    float* out = (float*)d_out;

    cudaFuncSetAttribute(gather_kernel,
                         cudaFuncAttributeMaxDynamicSharedMemorySize, SX_BYTES);

    prep_kernel<<<721, 256>>>(x, out, W1, b1, W2, b2);
    count_kernel<<<(NCONTRIB + 255) / 256, 256>>>(gi0, gi1, wc00, wc01, wc02,
                                                  wc10, wc11, wc12);
    scan_kernel<<<1, 1024>>>();
    fill_kernel<<<(NCONTRIB + 255) / 256, 256>>>(gi0, gi1, wc00, wc01, wc02,
                                                 wc10, wc11, wc12);
    gather_kernel<<<NCGRP * NTILES, 1024, SX_BYTES>>>(out);
}

// round 13
// speedup vs baseline: 1.3221x; 1.3221x over previous
#include <cuda_runtime.h>
#include <cuda_fp16.h>

// ---------------- geometry (fixed) -------------------------------------------
#define NCHANS   2560
#define T        256
#define CT       (NCHANS * T)        // 655360
#define NCELLS   40000
#define NCONTRIB (2 * NCELLS * 3)    // 240000
#define NSUB     4                   // sub-buckets per channel
#define NBUCK    (NCHANS * NSUB)     // 10240
#define CAP      64                  // slots per bucket (mean 23.4, +8 sigma)

// ---------------- gather tiling ----------------------------------------------
#define TW       16                  // ticks per tile (8 half2 pairs)
#define NTILES   (T / TW)            // 16
#define GCH      128                 // channels per gather block
#define NCGRP    (NCHANS / GCH)      // 20
#define SXP      10                  // smem pair-stride (half2 words, EVEN for LDS.64)
#define SX_BYTES (NCHANS * SXP * 4)  // 102400

// ---------------- device scratch (static; no allocations) --------------------
__device__ int      g_cnt[NBUCK];
__device__ int2     g_meta2[NBUCK * CAP];  // (ch0|ch1<<16, ch2) per contribution
__device__ unsigned g_xp[CT / 2];          // relu(x) fp16, pair-major: [t/2][ch]
__device__ float    g_M[6];                // collapsed W1@W2, M[p*2+o]
__device__ float    g_c[2];                // collapsed b1@W2 + b2

// ---------------- kernel A: prep — relu + fp16 pair-transpose + weights + zero
// blocks [0,640): 32x32 relu-transpose tiles; 640: weights; [641,681): zero cnt
__global__ void prep_kernel(const float* __restrict__ x, float* __restrict__ out,
                            const float* __restrict__ W1, const float* __restrict__ b1,
                            const float* __restrict__ W2, const float* __restrict__ b2) {
    int b = blockIdx.x;
    if (b < 640) {
        __shared__ float tile[32][33];                   // tile[ch_local][t_local]
        int cht = b % 80, tt = b / 80;
        int ch0 = cht * 32, t0 = tt * 32;
        int tx = threadIdx.x & 31, ty = threadIdx.x >> 5;   // 32 x 8
        #pragma unroll
        for (int r = 0; r < 4; r++) {
            int ch = ch0 + ty + 8 * r;
            float v = fmaxf(x[ch * T + t0 + tx], 0.f);
            out[ch * T + t0 + tx] = v;                       // feature 0 exact fp32
            tile[ty + 8 * r][tx] = v;
        }
        __syncthreads();
        #pragma unroll
        for (int rr = 0; rr < 2; rr++) {
            int tp = ty + 8 * rr;                            // tick-pair 0..15 in tile
            __half2 h = __floats2half2_rn(tile[tx][2 * tp], tile[tx][2 * tp + 1]);
            g_xp[(t0 / 2 + tp) * NCHANS + ch0 + tx] = *(unsigned*)&h;
        }
    } else if (b == 640) {
        if (threadIdx.x < 6) {
            int p = threadIdx.x >> 1, o = threadIdx.x & 1;
            float s = 0.f;
            #pragma unroll
            for (int h = 0; h < 8; h++) s = fmaf(W1[p * 8 + h], W2[h * 2 + o], s);
            g_M[threadIdx.x] = s;
        } else if (threadIdx.x < 8) {
            int o = threadIdx.x - 6;
            float s = b2[o];
            #pragma unroll
            for (int h = 0; h < 8; h++) s = fmaf(b1[h], W2[h * 2 + o], s);
            g_c[o] = s;
        }
    } else {
        int idx = (b - 641) * 256 + threadIdx.x;             // 40 blocks cover 10240
        if (idx < NBUCK) g_cnt[idx] = 0;
    }
}

// ---------------- kernel B: direct bucket fill (1 thread per contribution) ---
__global__ void fill_kernel(const int* __restrict__ gi0, const int* __restrict__ gi1,
                            const int* __restrict__ wc00, const int* __restrict__ wc01,
                            const int* __restrict__ wc02, const int* __restrict__ wc10,
                            const int* __restrict__ wc11, const int* __restrict__ wc12) {
    int e = blockIdx.x * blockDim.x + threadIdx.x;
    if (e >= NCONTRIB) return;
    int f = e / (NCELLS * 3);
    int r = e - f * (NCELLS * 3);          // cell*3 + p
    int p = r % 3;
    int r0 = r - p;                        // cell base
    const int* gi = f ? gi1 : gi0;
    int w0 = __ldg(&gi[r0 + 0]);
    int w1 = __ldg(&gi[r0 + 1]);
    int w2 = __ldg(&gi[r0 + 2]);
    const int* wcU = f ? wc10 : wc00;
    const int* wcV = f ? wc11 : wc01;
    const int* wcW = f ? wc12 : wc02;
    int c0 = __ldg(&wcU[2 * w0 + 1]);
    int c1 = __ldg(&wcV[2 * w1 + 1]);
    int c2 = __ldg(&wcW[2 * w2 + 1]);
    int cp = (p == 0) ? c0 : (p == 1) ? c1 : c2;   // own channel
    int bkt = cp * NSUB + (e & 3);
    int pos = atomicAdd(&g_cnt[bkt], 1);
    if (pos < CAP)
        g_meta2[bkt * CAP + pos] = make_int2(c0 | (c1 << 16), c2);
}

// ---------------- kernel C: fp16-slice gather + max --------------------------
// grid = 320, 512 threads. Block stages all 2560 channels x 8 half2 tick-pairs
// (102400 B, pair-stride 10 -> LDS.64-aligned). Thread = one channel x 4 ticks
// (2 adjacent pairs per plane via one LDS.64); warp spans 8 channels.
extern __shared__ unsigned sx2[];
__global__ void __launch_bounds__(512) gather_kernel(float* __restrict__ out) {
    const int cgrp = blockIdx.x % NCGRP;
    const int tile = blockIdx.x / NCGRP;
    const int t0 = tile * TW;

    // stage slice: g_xp[(t0/2 + pr)*2560 + ch] -> sx2[ch*10 + pr]
    {
        const unsigned* __restrict__ src = g_xp + (t0 / 2) * NCHANS;
        int j = threadIdx.x, ch = threadIdx.x, pr = 0;
        #pragma unroll
        for (int k = 0; k < (NCHANS * (TW / 2)) / 512; k++) {   // 40 iters
            sx2[ch * SXP + pr] = __ldg(src + j);
            j += 512; ch += 512;
            if (ch >= NCHANS) { ch -= NCHANS; ++pr; }
        }
    }
    __syncthreads();

    const int ln = threadIdx.x & 3;          // pair-chunk lane: pairs 2ln,2ln+1
    const int cl = threadIdx.x >> 2;         // channel lane 0..127
    const int c  = cgrp * GCH + cl;
    const int po = 2 * ln;                   // pair offset within row

    const float M00 = g_M[0], M01 = g_M[1];
    const float M10 = g_M[2], M11 = g_M[3];
    const float M20 = g_M[4], M21 = g_M[5];
    const float K0 = g_c[0], K1 = g_c[1];

    float m0 = 0.f, m1 = 0.f, m2 = 0.f, m3 = 0.f;   // out0, ticks 4ln..4ln+3
    float n0 = 0.f, n1 = 0.f, n2 = 0.f, n3 = 0.f;   // out1

    #pragma unroll
    for (int s = 0; s < NSUB; s++) {
        int bkt = c * NSUB + s;
        int len = min(g_cnt[bkt], CAP);
        const int2* __restrict__ mp = g_meta2 + bkt * CAP;
        #pragma unroll 2
        for (int i = 0; i < len; i++) {
            int2 mv = __ldg(mp + i);
            unsigned lo = (unsigned)mv.x;
            uint2 q0 = *(const uint2*)(sx2 + (lo & 0xFFFFu) * SXP + po);
            uint2 q1 = *(const uint2*)(sx2 + (lo >> 16)     * SXP + po);
            uint2 q2 = *(const uint2*)(sx2 + (unsigned)mv.y * SXP + po);
            float2 p0a = __half22float2(*(const __half2*)&q0.x);
            float2 p0b = __half22float2(*(const __half2*)&q0.y);
            float2 p1a = __half22float2(*(const __half2*)&q1.x);
            float2 p1b = __half22float2(*(const __half2*)&q1.y);
            float2 p2a = __half22float2(*(const __half2*)&q2.x);
            float2 p2b = __half22float2(*(const __half2*)&q2.y);
            m0 = fmaxf(m0, fmaf(p0a.x, M00, fmaf(p1a.x, M10, fmaf(p2a.x, M20, K0))));
            m1 = fmaxf(m1, fmaf(p0a.y, M00, fmaf(p1a.y, M10, fmaf(p2a.y, M20, K0))));
            m2 = fmaxf(m2, fmaf(p0b.x, M00, fmaf(p1b.x, M10, fmaf(p2b.x, M20, K0))));
            m3 = fmaxf(m3, fmaf(p0b.y, M00, fmaf(p1b.y, M10, fmaf(p2b.y, M20, K0))));
            n0 = fmaxf(n0, fmaf(p0a.x, M01, fmaf(p1a.x, M11, fmaf(p2a.x, M21, K1))));
            n1 = fmaxf(n1, fmaf(p0a.y, M01, fmaf(p1a.y, M11, fmaf(p2a.y, M21, K1))));
            n2 = fmaxf(n2, fmaf(p0b.x, M01, fmaf(p1b.x, M11, fmaf(p2b.x, M21, K1))));
            n3 = fmaxf(n3, fmaf(p0b.y, M01, fmaf(p1b.y, M11, fmaf(p2b.y, M21, K1))));
        }
    }

    const int tA = t0 + 4 * ln;              // 4 consecutive ticks, 16B aligned
    *(float4*)(out + CT + c * T + tA)     = make_float4(m0, m1, m2, m3);
    *(float4*)(out + 2 * CT + c * T + tA) = make_float4(n0, n1, n2, n3);
}

// ---------------- launch ------------------------------------------------------
extern "C" void kernel_launch(void* const* d_in, const int* in_sizes, int n_in,
                              void* d_out, int out_size) {
    const float* x   = (const float*)d_in[0];
    const float* W1  = (const float*)d_in[1];
    const float* b1  = (const float*)d_in[2];
    const float* W2  = (const float*)d_in[3];
    const float* b2  = (const float*)d_in[4];
    const int* gi0   = (const int*)d_in[5];
    const int* gi1   = (const int*)d_in[6];
    const int* wc00  = (const int*)d_in[7];
    const int* wc01  = (const int*)d_in[8];
    const int* wc02  = (const int*)d_in[9];
    const int* wc10  = (const int*)d_in[10];
    const int* wc11  = (const int*)d_in[11];
    const int* wc12  = (const int*)d_in[12];
    float* out = (float*)d_out;

    cudaFuncSetAttribute(gather_kernel,
                         cudaFuncAttributeMaxDynamicSharedMemorySize, SX_BYTES);

    prep_kernel<<<681, 256>>>(x, out, W1, b1, W2, b2);
    fill_kernel<<<(NCONTRIB + 255) / 256, 256>>>(gi0, gi1, wc00, wc01, wc02,
                                                 wc10, wc11, wc12);
    gather_kernel<<<NCGRP * NTILES, 512, SX_BYTES>>>(out);
}